// round 9
// baseline (speedup 1.0000x reference)
#include <cuda_runtime.h>
#include <cstdint>

// ---------------------------------------------------------------------------
// out = BN( sign(x) @ sign(W)^T ),  x[8192,2048], W[2048,2048] fp32.
// tcgen05 unavailable (harness assembles sm_103, not sm_103a):
// binarize -> int8 mma.sync GEMM (s32 accum, exact; column stats fused in
// epilogue; result stored int16) -> finalize -> normalize.
// 4 launches per call so ncu (-s 5 -c 1) lands on the GEMM of call #2.
// ---------------------------------------------------------------------------

static constexpr int Mdim = 8192;
static constexpr int Ndim = 2048;
static constexpr int Kdim = 2048;

__device__ int8_t  g_xa[(size_t)Mdim * Kdim];          // 16 MB
__device__ int8_t  g_wa[(size_t)Ndim * Kdim];          //  4 MB
__device__ int16_t g_gemm16[(size_t)Mdim * Ndim];      // 32 MB (|val| <= 2048)
__device__ float   g_psum[128 * Ndim];                 // per-64-row partials
__device__ float   g_psq [128 * Ndim];
__device__ float   g_scale[Ndim];
__device__ float   g_shift[Ndim];

// ---------------------------------------------------------------------------
// Helpers
// ---------------------------------------------------------------------------
__device__ __forceinline__ uint32_t smem_u32(const void* p) {
    uint32_t r;
    asm("{ .reg .u64 t; cvta.to.shared.u64 t, %1; cvt.u32.u64 %0, t; }"
        : "=r"(r) : "l"(p));
    return r;
}

__device__ __forceinline__ void cp16(uint32_t saddr, const void* gaddr) {
    asm volatile("cp.async.cg.shared.global [%0], [%1], 16;"
                 :: "r"(saddr), "l"(gaddr));
}

// SW128 swizzle for 128-byte rows: bits[6:4] ^= bits[9:7]
__device__ __forceinline__ uint32_t swz128(uint32_t off) {
    return off ^ ((off >> 3) & 0x70);
}

#define LDSM_X4(R0, R1, R2, R3, addr)                                        \
    asm volatile("ldmatrix.sync.aligned.m8n8.x4.shared.b16 {%0,%1,%2,%3}, [%4];" \
                 : "=r"(R0), "=r"(R1), "=r"(R2), "=r"(R3) : "r"(addr))

__device__ __forceinline__ void mma_s8(int& c0, int& c1, int& c2, int& c3,
                                       uint32_t a0, uint32_t a1, uint32_t a2,
                                       uint32_t a3, uint32_t b0, uint32_t b1) {
    asm volatile(
        "mma.sync.aligned.m16n8k32.row.col.s32.s8.s8.s32 "
        "{%0,%1,%2,%3}, {%4,%5,%6,%7}, {%8,%9}, {%0,%1,%2,%3};"
        : "+r"(c0), "+r"(c1), "+r"(c2), "+r"(c3)
        : "r"(a0), "r"(a1), "r"(a2), "r"(a3), "r"(b0), "r"(b1));
}

// ---------------------------------------------------------------------------
// Kernel 1: binarize both x and W (single launch)
// ---------------------------------------------------------------------------
__device__ __forceinline__ int8_t sgn8(float a) {
    return (int8_t)((a > 0.0f) ? 1 : ((a < 0.0f) ? -1 : 0));
}

__global__ void bin_kernel(const float4* __restrict__ x,
                           const float4* __restrict__ w) {
    const int nx4 = Mdim * Kdim / 4;
    int i = blockIdx.x * blockDim.x + threadIdx.x;
    if (i < nx4) {
        float4 v = x[i];
        reinterpret_cast<char4*>(g_xa)[i] =
            make_char4(sgn8(v.x), sgn8(v.y), sgn8(v.z), sgn8(v.w));
    } else {
        int j = i - nx4;
        float4 v = w[j];
        reinterpret_cast<char4*>(g_wa)[j] =
            make_char4(sgn8(v.x), sgn8(v.y), sgn8(v.z), sgn8(v.w));
    }
}

// ---------------------------------------------------------------------------
// Kernel 2: int8 GEMM  D = Xa @ Wa^T.  CTA 128x256, BK=128, 3-stage cp.async,
// 256 threads = 2x4 warps, warp tile 64x64, register-pipelined ldmatrix,
// column stats fused into epilogue, int16 result.
// ---------------------------------------------------------------------------
static constexpr int BM = 128, BN = 256, BK = 128, STAGES = 3;
static constexpr int KTILES = Kdim / BK;                  // 16
static constexpr int A_BYTES = BM * BK;                   // 16 KB
static constexpr int B_BYTES = BN * BK;                   // 32 KB
static constexpr int STAGE_BYTES = A_BYTES + B_BYTES;     // 48 KB
static constexpr int GEMM_SMEM = STAGES * STAGE_BYTES;    // 144 KB (dynamic)

__global__ void __launch_bounds__(256, 1)
gemm_kernel() {
    extern __shared__ __align__(1024) char smraw[];

    const int tid  = threadIdx.x;
    const int lane = tid & 31;
    const int wid  = tid >> 5;
    const int warpM = wid >> 2;            // 0..1 -> 64 rows
    const int warpN = wid & 3;             // 0..3 -> 64 cols
    const int tileM = blockIdx.y;          // 0..63
    const int tileN = blockIdx.x;          // 0..7

    const uint32_t smBase = smem_u32(smraw);

    const int8_t* gA = g_xa + (size_t)tileM * BM * Kdim;
    const int8_t* gB = g_wa + (size_t)tileN * BN * Kdim;

    auto load_stage = [&](int s, int kt) {
        uint32_t aBase = smBase + (uint32_t)s * STAGE_BYTES;
        uint32_t bBase = aBase + A_BYTES;
        // A: 1024 x 16B chunks / 256 thr (128B rows: row = c>>3, seg = c&7)
        #pragma unroll
        for (int i = 0; i < 4; i++) {
            int c = i * 256 + tid;
            int row = c >> 3, seg = c & 7;
            cp16(aBase + swz128((uint32_t)c * 16),
                 gA + (size_t)row * Kdim + kt * BK + seg * 16);
        }
        // B: 2048 x 16B chunks / 256 thr
        #pragma unroll
        for (int i = 0; i < 8; i++) {
            int c = i * 256 + tid;
            int row = c >> 3, seg = c & 7;
            cp16(bBase + swz128((uint32_t)c * 16),
                 gB + (size_t)row * Kdim + kt * BK + seg * 16);
        }
        asm volatile("cp.async.commit_group;" ::: "memory");
    };

    // ldmatrix lane addressing: lanes 0-7 rows 0-7 @k0, 8-15 rows 8-15 @k0,
    // 16-23 rows 0-7 @+16B, 24-31 rows 8-15 @+16B.
    const int lrow = (lane & 7) + (((lane >> 3) & 1) << 3);
    const int lkb  = ((lane >> 4) & 1) * 16;

    uint32_t aoff[4], boff[4];
    #pragma unroll
    for (int mi = 0; mi < 4; mi++)
        aoff[mi] = (uint32_t)(warpM * 64 + mi * 16 + lrow) * BK + lkb;
    #pragma unroll
    for (int p = 0; p < 4; p++)
        boff[p] = (uint32_t)(warpN * 64 + p * 16 + lrow) * BK + lkb;

    int acc[4][8][4];
    #pragma unroll
    for (int mi = 0; mi < 4; mi++)
        #pragma unroll
        for (int ni = 0; ni < 8; ni++)
            #pragma unroll
            for (int r = 0; r < 4; r++) acc[mi][ni][r] = 0;

    // prologue
    load_stage(0, 0);
    load_stage(1, 1);

    uint32_t a[2][4][4], b[2][4][4];   // double-buffered fragments

    for (int kt = 0; kt < KTILES; kt++) {
        const int s = kt % 3;
        asm volatile("cp.async.wait_group %0;" :: "n"(1) : "memory");
        __syncthreads();

        const int nk = kt + 2;
        if (nk < KTILES) {
            load_stage(nk % 3, nk);     // overwrites slot consumed at kt-1
        } else {
            asm volatile("cp.async.commit_group;" ::: "memory");
        }

        const uint32_t aBase = smBase + (uint32_t)s * STAGE_BYTES;
        const uint32_t bBase = aBase + A_BYTES;

        // prefetch k32 step 0
        #pragma unroll
        for (int mi = 0; mi < 4; mi++)
            LDSM_X4(a[0][mi][0], a[0][mi][1], a[0][mi][2], a[0][mi][3],
                    aBase + swz128(aoff[mi]));
        #pragma unroll
        for (int p = 0; p < 4; p++)
            LDSM_X4(b[0][p][0], b[0][p][1], b[0][p][2], b[0][p][3],
                    bBase + swz128(boff[p]));

        #pragma unroll
        for (int k32 = 0; k32 < 4; k32++) {
            const int cur = k32 & 1, nxt = cur ^ 1;
            if (k32 < 3) {
                #pragma unroll
                for (int mi = 0; mi < 4; mi++)
                    LDSM_X4(a[nxt][mi][0], a[nxt][mi][1],
                            a[nxt][mi][2], a[nxt][mi][3],
                            aBase + swz128(aoff[mi] + (k32 + 1) * 32));
                #pragma unroll
                for (int p = 0; p < 4; p++)
                    LDSM_X4(b[nxt][p][0], b[nxt][p][1],
                            b[nxt][p][2], b[nxt][p][3],
                            bBase + swz128(boff[p] + (k32 + 1) * 32));
            }
            #pragma unroll
            for (int mi = 0; mi < 4; mi++) {
                #pragma unroll
                for (int ni = 0; ni < 8; ni++) {
                    const int p = ni >> 1, sub = ni & 1;
                    mma_s8(acc[mi][ni][0], acc[mi][ni][1],
                           acc[mi][ni][2], acc[mi][ni][3],
                           a[cur][mi][0], a[cur][mi][1],
                           a[cur][mi][2], a[cur][mi][3],
                           b[cur][p][sub], b[cur][p][2 + sub]);
                }
            }
        }
    }

    // ---------------- Epilogue ----------------
    // acc layout: c0,c1 -> (row = mi*16 + lane>>2, col = ni*8 + 2*(lane&3) +{0,1})
    //             c2,c3 -> row+8, same cols.
    const int erow = lane >> 2;
    const int ecol = (lane & 3) * 2;
    const int rowBase = tileM * BM + warpM * 64;
    const int colBase = tileN * BN + warpN * 64;

    int16_t* gout = g_gemm16 + (size_t)rowBase * Ndim + colBase;
    #pragma unroll
    for (int mi = 0; mi < 4; mi++) {
        #pragma unroll
        for (int ni = 0; ni < 8; ni++) {
            int16_t* p0 = gout + (size_t)(mi * 16 + erow) * Ndim + ni * 8 + ecol;
            *reinterpret_cast<short2*>(p0) =
                make_short2((int16_t)acc[mi][ni][0], (int16_t)acc[mi][ni][1]);
            *reinterpret_cast<short2*>(p0 + (size_t)8 * Ndim) =
                make_short2((int16_t)acc[mi][ni][2], (int16_t)acc[mi][ni][3]);
        }
    }

    // fused per-64-row column stats
    const int chunk = tileM * 2 + warpM;        // 0..127
    #pragma unroll
    for (int ni = 0; ni < 8; ni++) {
        float s0 = 0.f, s1 = 0.f, q0 = 0.f, q1 = 0.f;
        #pragma unroll
        for (int mi = 0; mi < 4; mi++) {
            float v0 = (float)acc[mi][ni][0];
            float v1 = (float)acc[mi][ni][1];
            float v2 = (float)acc[mi][ni][2];
            float v3 = (float)acc[mi][ni][3];
            s0 += v0 + v2;  s1 += v1 + v3;
            q0 += v0 * v0 + v2 * v2;
            q1 += v1 * v1 + v3 * v3;
        }
        #pragma unroll
        for (int off = 4; off < 32; off <<= 1) {
            s0 += __shfl_xor_sync(0xffffffffu, s0, off);
            s1 += __shfl_xor_sync(0xffffffffu, s1, off);
            q0 += __shfl_xor_sync(0xffffffffu, q0, off);
            q1 += __shfl_xor_sync(0xffffffffu, q1, off);
        }
        if (lane < 4) {
            int c = colBase + ni * 8 + lane * 2;
            g_psum[(size_t)chunk * Ndim + c]     = s0;
            g_psum[(size_t)chunk * Ndim + c + 1] = s1;
            g_psq [(size_t)chunk * Ndim + c]     = q0;
            g_psq [(size_t)chunk * Ndim + c + 1] = q1;
        }
    }
}

// ---------------------------------------------------------------------------
// Kernel 3: finalize stats -> per-column scale/shift
// 256 threads = 64 cols x 4 depth-slices; shfl-combine within quads.
// ---------------------------------------------------------------------------
__global__ void finalize_kernel(const float* __restrict__ gamma,
                                const float* __restrict__ beta) {
    int t = threadIdx.x;
    int col = blockIdx.x * 64 + (t >> 2);
    int slice = t & 3;
    float s = 0.f, q = 0.f;
    #pragma unroll 8
    for (int i = slice * 32; i < slice * 32 + 32; i++) {
        s += g_psum[(size_t)i * Ndim + col];
        q += g_psq [(size_t)i * Ndim + col];
    }
    s += __shfl_xor_sync(0xffffffffu, s, 1);
    q += __shfl_xor_sync(0xffffffffu, q, 1);
    s += __shfl_xor_sync(0xffffffffu, s, 2);
    q += __shfl_xor_sync(0xffffffffu, q, 2);
    if (slice == 0) {
        const float invB = 1.0f / (float)Mdim;
        float mean = s * invB;
        float var  = q * invB - mean * mean;
        float inv  = rsqrtf(var + 1e-5f);
        float sc   = gamma[col] * inv;
        g_scale[col] = sc;
        g_shift[col] = beta[col] - mean * sc;
    }
}

// ---------------------------------------------------------------------------
// Kernel 4: normalize into d_out (reads int16 gemm result)
// ---------------------------------------------------------------------------
__global__ void normalize_kernel(float4* __restrict__ out) {
    int i = blockIdx.x * blockDim.x + threadIdx.x;
    int c0 = (i * 4) & (Ndim - 1);
    short4 v = reinterpret_cast<const short4*>(g_gemm16)[i];
    float4 o;
    o.x = (float)v.x * g_scale[c0 + 0] + g_shift[c0 + 0];
    o.y = (float)v.y * g_scale[c0 + 1] + g_shift[c0 + 1];
    o.z = (float)v.z * g_scale[c0 + 2] + g_shift[c0 + 2];
    o.w = (float)v.w * g_scale[c0 + 3] + g_shift[c0 + 3];
    out[i] = o;
}

// ---------------------------------------------------------------------------
// Launch (4 launches per call so ncu -s 5 captures call #2's GEMM)
// ---------------------------------------------------------------------------
extern "C" void kernel_launch(void* const* d_in, const int* in_sizes, int n_in,
                              void* d_out, int out_size) {
    const float* x     = (const float*)d_in[0];
    const float* w     = (const float*)d_in[1];
    const float* gamma = (const float*)d_in[2];
    const float* beta  = (const float*)d_in[3];
    float* out = (float*)d_out;

    cudaFuncSetAttribute(gemm_kernel,
                         cudaFuncAttributeMaxDynamicSharedMemorySize, GEMM_SMEM);

    const int nbin = (Mdim * Kdim + Ndim * Kdim) / 4;   // float4 elements
    bin_kernel<<<nbin / 256, 256>>>((const float4*)x, (const float4*)w);

    dim3 ggrid(Ndim / BN, Mdim / BM);   // (8, 64)
    gemm_kernel<<<ggrid, 256, GEMM_SMEM>>>();

    finalize_kernel<<<Ndim / 64, 256>>>(gamma, beta);
    normalize_kernel<<<(Mdim * Ndim / 4) / 256, 256>>>((float4*)out);
}

// round 10
// speedup vs baseline: 1.0967x; 1.0967x over previous
#include <cuda_runtime.h>
#include <cstdint>

// ---------------------------------------------------------------------------
// out = BN( sign(x) @ sign(W)^T ),  x[8192,2048], W[2048,2048] fp32.
// tcgen05 unavailable (harness assembles sm_103, not sm_103a). Legacy int8
// mma.sync measured at ~64 cyc/SMSP (quarter rate) -> GEMM is pipe-ceiling
// bound; this round removes wave-quantization tail with a persistent GEMM
// (148 CTAs, cp.async pipeline flattened across tile boundaries).
// Launch order puts the GEMM 4th so ncu's fixed skip finally captures it.
// ---------------------------------------------------------------------------

static constexpr int Mdim = 8192;
static constexpr int Ndim = 2048;
static constexpr int Kdim = 2048;

__device__ int8_t  g_xa[(size_t)Mdim * Kdim];          // 16 MB
__device__ int8_t  g_wa[(size_t)Ndim * Kdim];          //  4 MB
__device__ int16_t g_gemm16[(size_t)Mdim * Ndim];      // 32 MB (|val| <= 2048)
__device__ float   g_psum[128 * Ndim];                 // per-64-row partials
__device__ float   g_psq [128 * Ndim];
__device__ float   g_scale[Ndim];
__device__ float   g_shift[Ndim];

// ---------------------------------------------------------------------------
// Helpers
// ---------------------------------------------------------------------------
__device__ __forceinline__ uint32_t smem_u32(const void* p) {
    uint32_t r;
    asm("{ .reg .u64 t; cvta.to.shared.u64 t, %1; cvt.u32.u64 %0, t; }"
        : "=r"(r) : "l"(p));
    return r;
}

__device__ __forceinline__ void cp16(uint32_t saddr, const void* gaddr) {
    asm volatile("cp.async.cg.shared.global [%0], [%1], 16;"
                 :: "r"(saddr), "l"(gaddr));
}

// SW64 swizzle for 64-byte rows: bits[5:4] ^= bits[8:7]
__device__ __forceinline__ uint32_t swz64(uint32_t off) {
    return off ^ ((off >> 3) & 0x30);
}

#define LDSM_X4(R0, R1, R2, R3, addr)                                        \
    asm volatile("ldmatrix.sync.aligned.m8n8.x4.shared.b16 {%0,%1,%2,%3}, [%4];" \
                 : "=r"(R0), "=r"(R1), "=r"(R2), "=r"(R3) : "r"(addr))

__device__ __forceinline__ void mma_s8(int& c0, int& c1, int& c2, int& c3,
                                       uint32_t a0, uint32_t a1, uint32_t a2,
                                       uint32_t a3, uint32_t b0, uint32_t b1) {
    asm volatile(
        "mma.sync.aligned.m16n8k32.row.col.s32.s8.s8.s32 "
        "{%0,%1,%2,%3}, {%4,%5,%6,%7}, {%8,%9}, {%0,%1,%2,%3};"
        : "+r"(c0), "+r"(c1), "+r"(c2), "+r"(c3)
        : "r"(a0), "r"(a1), "r"(a2), "r"(a3), "r"(b0), "r"(b1));
}

// ---------------------------------------------------------------------------
// Kernels 1/2: binarize fp32 -> int8 {-1, 0, +1}
// ---------------------------------------------------------------------------
__device__ __forceinline__ int8_t sgn8(float a) {
    return (int8_t)((a > 0.0f) ? 1 : ((a < 0.0f) ? -1 : 0));
}

__global__ void binx_kernel(const float4* __restrict__ in) {
    int i = blockIdx.x * blockDim.x + threadIdx.x;
    float4 v = in[i];
    reinterpret_cast<char4*>(g_xa)[i] =
        make_char4(sgn8(v.x), sgn8(v.y), sgn8(v.z), sgn8(v.w));
}

__global__ void binw_kernel(const float4* __restrict__ in) {
    int i = blockIdx.x * blockDim.x + threadIdx.x;
    float4 v = in[i];
    reinterpret_cast<char4*>(g_wa)[i] =
        make_char4(sgn8(v.x), sgn8(v.y), sgn8(v.z), sgn8(v.w));
}

// Launch-slot filler so the GEMM sits at ncu's captured position (#4).
// Zeroes a few stats words that the GEMM epilogue rewrites anyway.
__global__ void pad_kernel() {
    g_psum[threadIdx.x] = 0.f;
}

// ---------------------------------------------------------------------------
// Kernel 4 (launch position): persistent int8 GEMM, D = Xa @ Wa^T.
// 148 CTAs (1/SM), each owns ceil-share of the 64x16=1024 (128x128) tiles.
// BK=64, 4-stage cp.async pipeline flattened across tile boundaries.
// 256 threads = 2x4 warps, warp tile 64x32 (best-measured R7 inner loop).
// Column stats fused into epilogue; result stored int16.
// ---------------------------------------------------------------------------
static constexpr int BM = 128, BN = 128, BK = 64, STAGES = 4;
static constexpr int KT = Kdim / BK;                      // 32 ktiles / tile
static constexpr int NTILES = (Mdim / BM) * (Ndim / BN);  // 1024
static constexpr int NWORK = 148;                         // persistent CTAs
static constexpr int A_BYTES = BM * BK;                   // 8 KB
static constexpr int B_BYTES = BN * BK;                   // 8 KB
static constexpr int STAGE_BYTES = A_BYTES + B_BYTES;     // 16 KB
static constexpr int GEMM_SMEM = STAGES * STAGE_BYTES;    // 64 KB

__global__ void __launch_bounds__(256, 1)
gemm_kernel() {
    __shared__ __align__(1024) char smraw[GEMM_SMEM];

    const int tid  = threadIdx.x;
    const int lane = tid & 31;
    const int wid  = tid >> 5;
    const int warpM = wid >> 2;            // 0..1 -> 64 rows
    const int warpN = wid & 3;             // 0..3 -> 32 cols
    const int bid  = blockIdx.x;

    const uint32_t smBase = smem_u32(smraw);

    // tiles owned by this worker: bid, bid+148, ... (136 workers get 7, 12 get 6)
    const int nt = (NTILES / NWORK) + (bid < (NTILES % NWORK) ? 1 : 0);
    const int P  = nt * KT;                // flattened stream length

    // stream position p -> (tile j = p>>5, ktile kt = p&31)
    auto load_pos = [&](int s, int p) {
        const int j  = p >> 5;
        const int kt = p & (KT - 1);
        const int t  = bid + NWORK * j;
        const int8_t* gA = g_xa + (size_t)(t >> 4) * BM * Kdim + kt * BK;
        const int8_t* gB = g_wa + (size_t)(t & 15) * BN * Kdim + kt * BK;
        uint32_t aBase = smBase + (uint32_t)s * STAGE_BYTES;
        uint32_t bBase = aBase + A_BYTES;
        #pragma unroll
        for (int i = 0; i < 2; i++) {       // A: 512 x 16B chunks / 256 thr
            int c = i * 256 + tid;
            int row = c >> 2, seg = c & 3;
            cp16(aBase + swz64((uint32_t)c * 16),
                 gA + (size_t)row * Kdim + seg * 16);
        }
        #pragma unroll
        for (int i = 0; i < 2; i++) {       // B
            int c = i * 256 + tid;
            int row = c >> 2, seg = c & 3;
            cp16(bBase + swz64((uint32_t)c * 16),
                 gB + (size_t)row * Kdim + seg * 16);
        }
        asm volatile("cp.async.commit_group;" ::: "memory");
    };

    // ldmatrix lane addressing: lanes 0-7 rows 0-7 @k0, 8-15 rows 8-15 @k0,
    // 16-23 rows 0-7 @+16B, 24-31 rows 8-15 @+16B.
    const int lrow = (lane & 7) + (((lane >> 3) & 1) << 3);
    const int lkb  = ((lane >> 4) & 1) * 16;

    uint32_t aoff[4], boff[2];
    #pragma unroll
    for (int mi = 0; mi < 4; mi++)
        aoff[mi] = (uint32_t)(warpM * 64 + mi * 16 + lrow) * BK + lkb;
    #pragma unroll
    for (int pb = 0; pb < 2; pb++)
        boff[pb] = (uint32_t)(warpN * 32 + pb * 16 + lrow) * BK + lkb;

    int acc[4][4][4];
    #pragma unroll
    for (int mi = 0; mi < 4; mi++)
        #pragma unroll
        for (int ni = 0; ni < 4; ni++)
            #pragma unroll
            for (int r = 0; r < 4; r++) acc[mi][ni][r] = 0;

    const int erow = lane >> 2;
    const int ecol = (lane & 3) * 2;

    // prologue: fill stages 0..2 (P >= 6*32, always enough positions)
    #pragma unroll
    for (int s = 0; s < STAGES - 1; s++) load_pos(s, s);

    for (int p = 0; p < P; p++) {
        const int s = p & (STAGES - 1);
        asm volatile("cp.async.wait_group %0;" :: "n"(STAGES - 2) : "memory");
        __syncthreads();

        const int np = p + STAGES - 1;
        if (np < P) {
            load_pos(np & (STAGES - 1), np);
        } else {
            asm volatile("cp.async.commit_group;" ::: "memory");
        }

        const uint32_t aBase = smBase + (uint32_t)s * STAGE_BYTES;
        const uint32_t bBase = aBase + A_BYTES;

        #pragma unroll
        for (int k32 = 0; k32 < 2; k32++) {
            uint32_t a[4][4], b[2][4];
            #pragma unroll
            for (int mi = 0; mi < 4; mi++) {
                LDSM_X4(a[mi][0], a[mi][1], a[mi][2], a[mi][3],
                        aBase + swz64(aoff[mi] + k32 * 32));
            }
            #pragma unroll
            for (int pb = 0; pb < 2; pb++) {
                LDSM_X4(b[pb][0], b[pb][1], b[pb][2], b[pb][3],
                        bBase + swz64(boff[pb] + k32 * 32));
            }
            #pragma unroll
            for (int mi = 0; mi < 4; mi++) {
                #pragma unroll
                for (int ni = 0; ni < 4; ni++) {
                    const int pb = ni >> 1, sub = ni & 1;
                    mma_s8(acc[mi][ni][0], acc[mi][ni][1],
                           acc[mi][ni][2], acc[mi][ni][3],
                           a[mi][0], a[mi][1], a[mi][2], a[mi][3],
                           b[pb][sub], b[pb][2 + sub]);
                }
            }
        }

        if ((p & (KT - 1)) == KT - 1) {
            // ---- tile epilogue: int16 store + fused column stats ----
            const int t = bid + NWORK * (p >> 5);
            const int tileM = t >> 4, tileN = t & 15;
            const int rowBase = tileM * BM + warpM * 64;
            const int colBase = tileN * BN + warpN * 32;

            int16_t* gout = g_gemm16 + (size_t)rowBase * Ndim + colBase;
            #pragma unroll
            for (int mi = 0; mi < 4; mi++) {
                #pragma unroll
                for (int ni = 0; ni < 4; ni++) {
                    int16_t* p0 = gout + (size_t)(mi * 16 + erow) * Ndim
                                + ni * 8 + ecol;
                    *reinterpret_cast<short2*>(p0) =
                        make_short2((int16_t)acc[mi][ni][0],
                                    (int16_t)acc[mi][ni][1]);
                    *reinterpret_cast<short2*>(p0 + (size_t)8 * Ndim) =
                        make_short2((int16_t)acc[mi][ni][2],
                                    (int16_t)acc[mi][ni][3]);
                }
            }

            const int chunk = tileM * 2 + warpM;    // 0..127
            #pragma unroll
            for (int ni = 0; ni < 4; ni++) {
                float s0 = 0.f, s1 = 0.f, q0 = 0.f, q1 = 0.f;
                #pragma unroll
                for (int mi = 0; mi < 4; mi++) {
                    float v0 = (float)acc[mi][ni][0];
                    float v1 = (float)acc[mi][ni][1];
                    float v2 = (float)acc[mi][ni][2];
                    float v3 = (float)acc[mi][ni][3];
                    s0 += v0 + v2;  s1 += v1 + v3;
                    q0 += v0 * v0 + v2 * v2;
                    q1 += v1 * v1 + v3 * v3;
                }
                #pragma unroll
                for (int off = 4; off < 32; off <<= 1) {
                    s0 += __shfl_xor_sync(0xffffffffu, s0, off);
                    s1 += __shfl_xor_sync(0xffffffffu, s1, off);
                    q0 += __shfl_xor_sync(0xffffffffu, q0, off);
                    q1 += __shfl_xor_sync(0xffffffffu, q1, off);
                }
                if (lane < 4) {
                    int c = colBase + ni * 8 + lane * 2;
                    g_psum[(size_t)chunk * Ndim + c]     = s0;
                    g_psum[(size_t)chunk * Ndim + c + 1] = s1;
                    g_psq [(size_t)chunk * Ndim + c]     = q0;
                    g_psq [(size_t)chunk * Ndim + c + 1] = q1;
                }
            }

            #pragma unroll
            for (int mi = 0; mi < 4; mi++)
                #pragma unroll
                for (int ni = 0; ni < 4; ni++)
                    #pragma unroll
                    for (int r = 0; r < 4; r++) acc[mi][ni][r] = 0;
        }
    }
}

// ---------------------------------------------------------------------------
// Kernel 5: finalize stats -> per-column scale/shift
// ---------------------------------------------------------------------------
__global__ void finalize_kernel(const float* __restrict__ gamma,
                                const float* __restrict__ beta) {
    int t = threadIdx.x;
    int col = blockIdx.x * 64 + (t >> 2);
    int slice = t & 3;
    float s = 0.f, q = 0.f;
    #pragma unroll 8
    for (int i = slice * 32; i < slice * 32 + 32; i++) {
        s += g_psum[(size_t)i * Ndim + col];
        q += g_psq [(size_t)i * Ndim + col];
    }
    s += __shfl_xor_sync(0xffffffffu, s, 1);
    q += __shfl_xor_sync(0xffffffffu, q, 1);
    s += __shfl_xor_sync(0xffffffffu, s, 2);
    q += __shfl_xor_sync(0xffffffffu, q, 2);
    if (slice == 0) {
        const float invB = 1.0f / (float)Mdim;
        float mean = s * invB;
        float var  = q * invB - mean * mean;
        float inv  = rsqrtf(var + 1e-5f);
        float sc   = gamma[col] * inv;
        g_scale[col] = sc;
        g_shift[col] = beta[col] - mean * sc;
    }
}

// ---------------------------------------------------------------------------
// Kernel 6: normalize into d_out — float4 scale/shift loads (was L1-bound
// at 75% from 8 scalar LDGs/thread)
// ---------------------------------------------------------------------------
__global__ void normalize_kernel(float4* __restrict__ out) {
    int i = blockIdx.x * blockDim.x + threadIdx.x;
    int c4 = i & (Ndim / 4 - 1);
    short4 v = reinterpret_cast<const short4*>(g_gemm16)[i];
    float4 sc = reinterpret_cast<const float4*>(g_scale)[c4];
    float4 sh = reinterpret_cast<const float4*>(g_shift)[c4];
    float4 o;
    o.x = (float)v.x * sc.x + sh.x;
    o.y = (float)v.y * sc.y + sh.y;
    o.z = (float)v.z * sc.z + sh.z;
    o.w = (float)v.w * sc.w + sh.w;
    out[i] = o;
}

// ---------------------------------------------------------------------------
// Launch (GEMM at position 4 = ncu's observed capture slot)
// ---------------------------------------------------------------------------
extern "C" void kernel_launch(void* const* d_in, const int* in_sizes, int n_in,
                              void* d_out, int out_size) {
    const float* x     = (const float*)d_in[0];
    const float* w     = (const float*)d_in[1];
    const float* gamma = (const float*)d_in[2];
    const float* beta  = (const float*)d_in[3];
    float* out = (float*)d_out;

    binx_kernel<<<(Mdim * Kdim / 4) / 256, 256>>>((const float4*)x);   // 1
    binw_kernel<<<(Ndim * Kdim / 4) / 256, 256>>>((const float4*)w);   // 2
    pad_kernel<<<1, 32>>>();                                           // 3
    gemm_kernel<<<NWORK, 256>>>();                                     // 4
    finalize_kernel<<<Ndim / 64, 256>>>(gamma, beta);                  // 5
    normalize_kernel<<<(Mdim * Ndim / 4) / 256, 256>>>((float4*)out);  // 6
}

// round 11
// speedup vs baseline: 1.1266x; 1.0273x over previous
#include <cuda_runtime.h>
#include <cstdint>

// ---------------------------------------------------------------------------
// out = BN( sign(x) @ sign(W)^T ),  x[8192,2048], W[2048,2048] fp32.
// tcgen05 unavailable (harness assembles sm_103). Legacy int8 mma.sync is
// pipe-ceiling bound (R10 ncu: tensor=86.9%, DRAM=0.5%). This round: 2 CTAs/SM
// (16 warps) to cover barrier/ldsm/epilogue gaps, with SM-aware tile pairing
// (bid and bid+148 co-reside -> per-SM tile count balanced at 7).
// ---------------------------------------------------------------------------

static constexpr int Mdim = 8192;
static constexpr int Ndim = 2048;
static constexpr int Kdim = 2048;

__device__ int8_t  g_xa[(size_t)Mdim * Kdim];          // 16 MB
__device__ int8_t  g_wa[(size_t)Ndim * Kdim];          //  4 MB
__device__ int16_t g_gemm16[(size_t)Mdim * Ndim];      // 32 MB (|val| <= 2048)
__device__ float   g_psum[128 * Ndim];                 // per-64-row partials
__device__ float   g_psq [128 * Ndim];
__device__ float   g_scale[Ndim];
__device__ float   g_shift[Ndim];

// ---------------------------------------------------------------------------
// Helpers
// ---------------------------------------------------------------------------
__device__ __forceinline__ uint32_t smem_u32(const void* p) {
    uint32_t r;
    asm("{ .reg .u64 t; cvta.to.shared.u64 t, %1; cvt.u32.u64 %0, t; }"
        : "=r"(r) : "l"(p));
    return r;
}

__device__ __forceinline__ void cp16(uint32_t saddr, const void* gaddr) {
    asm volatile("cp.async.cg.shared.global [%0], [%1], 16;"
                 :: "r"(saddr), "l"(gaddr));
}

// SW64 swizzle for 64-byte rows: bits[5:4] ^= bits[8:7]
__device__ __forceinline__ uint32_t swz64(uint32_t off) {
    return off ^ ((off >> 3) & 0x30);
}

#define LDSM_X4(R0, R1, R2, R3, addr)                                        \
    asm volatile("ldmatrix.sync.aligned.m8n8.x4.shared.b16 {%0,%1,%2,%3}, [%4];" \
                 : "=r"(R0), "=r"(R1), "=r"(R2), "=r"(R3) : "r"(addr))

__device__ __forceinline__ void mma_s8(int& c0, int& c1, int& c2, int& c3,
                                       uint32_t a0, uint32_t a1, uint32_t a2,
                                       uint32_t a3, uint32_t b0, uint32_t b1) {
    asm volatile(
        "mma.sync.aligned.m16n8k32.row.col.s32.s8.s8.s32 "
        "{%0,%1,%2,%3}, {%4,%5,%6,%7}, {%8,%9}, {%0,%1,%2,%3};"
        : "+r"(c0), "+r"(c1), "+r"(c2), "+r"(c3)
        : "r"(a0), "r"(a1), "r"(a2), "r"(a3), "r"(b0), "r"(b1));
}

// ---------------------------------------------------------------------------
// Kernels 1/2: binarize fp32 -> int8 {-1, 0, +1}
// ---------------------------------------------------------------------------
__device__ __forceinline__ int8_t sgn8(float a) {
    return (int8_t)((a > 0.0f) ? 1 : ((a < 0.0f) ? -1 : 0));
}

__global__ void binx_kernel(const float4* __restrict__ in) {
    int i = blockIdx.x * blockDim.x + threadIdx.x;
    float4 v = in[i];
    reinterpret_cast<char4*>(g_xa)[i] =
        make_char4(sgn8(v.x), sgn8(v.y), sgn8(v.z), sgn8(v.w));
}

__global__ void binw_kernel(const float4* __restrict__ in) {
    int i = blockIdx.x * blockDim.x + threadIdx.x;
    float4 v = in[i];
    reinterpret_cast<char4*>(g_wa)[i] =
        make_char4(sgn8(v.x), sgn8(v.y), sgn8(v.z), sgn8(v.w));
}

// Launch-slot filler so the GEMM stays at ncu's captured position (#4).
__global__ void pad_kernel() {
    g_psum[threadIdx.x] = 0.f;
}

// ---------------------------------------------------------------------------
// Kernel 4: persistent int8 GEMM, D = Xa @ Wa^T.
// 296 CTAs (2/SM, bid and bid+148 co-resident per LUT_classic[bid%148]).
// Each SM owns a contiguous slab of 7 (or 6) 128x128 tiles, split 4+3 (3+3)
// between its two CTAs. BK=64, 4-stage cp.async flattened across tiles,
// 256 thr = 2x4 warps, warp tile 64x32, stats fused, int16 result.
// ---------------------------------------------------------------------------
static constexpr int BM = 128, BN = 128, BK = 64, STAGES = 4;
static constexpr int KT = Kdim / BK;                      // 32 ktiles / tile
static constexpr int NSM = 148;
static constexpr int NTILES = (Mdim / BM) * (Ndim / BN);  // 1024
static constexpr int FULL7 = NTILES - 6 * NSM;            // 136 SMs own 7 tiles
static constexpr int A_BYTES = BM * BK;                   // 8 KB
static constexpr int B_BYTES = BN * BK;                   // 8 KB
static constexpr int STAGE_BYTES = A_BYTES + B_BYTES;     // 16 KB
static constexpr int GEMM_SMEM = STAGES * STAGE_BYTES;    // 64 KB

__global__ void __launch_bounds__(256, 2)
gemm_kernel() {
    __shared__ __align__(1024) char smraw[GEMM_SMEM];

    const int tid  = threadIdx.x;
    const int lane = tid & 31;
    const int wid  = tid >> 5;
    const int warpM = wid >> 2;            // 0..1 -> 64 rows
    const int warpN = wid & 3;             // 0..3 -> 32 cols
    const int bid  = blockIdx.x;

    const uint32_t smBase = smem_u32(smraw);

    // SM-aware tile slab: bid%148 -> SM slab, bid/148 -> which co-resident CTA
    const int sm    = bid % NSM;
    const int which = bid / NSM;
    const int base  = (sm < FULL7) ? sm * 7 : FULL7 * 7 + (sm - FULL7) * 6;
    const int cnt   = (sm < FULL7) ? 7 : 6;
    const int halfc = (cnt + 1) >> 1;                    // 4 or 3
    const int start = which ? base + halfc : base;
    const int nt    = which ? cnt - halfc : halfc;       // 3 or 4
    const int P     = nt * KT;                           // flattened stream

    auto load_pos = [&](int s, int p) {
        const int j  = p >> 5;
        const int kt = p & (KT - 1);
        const int t  = start + j;
        const int8_t* gA = g_xa + (size_t)(t >> 4) * BM * Kdim + kt * BK;
        const int8_t* gB = g_wa + (size_t)(t & 15) * BN * Kdim + kt * BK;
        uint32_t aBase = smBase + (uint32_t)s * STAGE_BYTES;
        uint32_t bBase = aBase + A_BYTES;
        #pragma unroll
        for (int i = 0; i < 2; i++) {       // A: 512 x 16B chunks / 256 thr
            int c = i * 256 + tid;
            int row = c >> 2, seg = c & 3;
            cp16(aBase + swz64((uint32_t)c * 16),
                 gA + (size_t)row * Kdim + seg * 16);
        }
        #pragma unroll
        for (int i = 0; i < 2; i++) {       // B
            int c = i * 256 + tid;
            int row = c >> 2, seg = c & 3;
            cp16(bBase + swz64((uint32_t)c * 16),
                 gB + (size_t)row * Kdim + seg * 16);
        }
        asm volatile("cp.async.commit_group;" ::: "memory");
    };

    // ldmatrix lane addressing: lanes 0-7 rows 0-7 @k0, 8-15 rows 8-15 @k0,
    // 16-23 rows 0-7 @+16B, 24-31 rows 8-15 @+16B.
    const int lrow = (lane & 7) + (((lane >> 3) & 1) << 3);
    const int lkb  = ((lane >> 4) & 1) * 16;

    uint32_t aoff[4], boff[2];
    #pragma unroll
    for (int mi = 0; mi < 4; mi++)
        aoff[mi] = (uint32_t)(warpM * 64 + mi * 16 + lrow) * BK + lkb;
    #pragma unroll
    for (int pb = 0; pb < 2; pb++)
        boff[pb] = (uint32_t)(warpN * 32 + pb * 16 + lrow) * BK + lkb;

    int acc[4][4][4];
    #pragma unroll
    for (int mi = 0; mi < 4; mi++)
        #pragma unroll
        for (int ni = 0; ni < 4; ni++)
            #pragma unroll
            for (int r = 0; r < 4; r++) acc[mi][ni][r] = 0;

    const int erow = lane >> 2;
    const int ecol = (lane & 3) * 2;

    // prologue (P >= 96 always)
    #pragma unroll
    for (int s = 0; s < STAGES - 1; s++) load_pos(s, s);

    for (int p = 0; p < P; p++) {
        const int s = p & (STAGES - 1);
        asm volatile("cp.async.wait_group %0;" :: "n"(STAGES - 2) : "memory");
        __syncthreads();

        const int np = p + STAGES - 1;
        if (np < P) {
            load_pos(np & (STAGES - 1), np);
        } else {
            asm volatile("cp.async.commit_group;" ::: "memory");
        }

        const uint32_t aBase = smBase + (uint32_t)s * STAGE_BYTES;
        const uint32_t bBase = aBase + A_BYTES;

        #pragma unroll
        for (int k32 = 0; k32 < 2; k32++) {
            uint32_t a[4][4], b[2][4];
            #pragma unroll
            for (int mi = 0; mi < 4; mi++) {
                LDSM_X4(a[mi][0], a[mi][1], a[mi][2], a[mi][3],
                        aBase + swz64(aoff[mi] + k32 * 32));
            }
            #pragma unroll
            for (int pb = 0; pb < 2; pb++) {
                LDSM_X4(b[pb][0], b[pb][1], b[pb][2], b[pb][3],
                        bBase + swz64(boff[pb] + k32 * 32));
            }
            #pragma unroll
            for (int mi = 0; mi < 4; mi++) {
                #pragma unroll
                for (int ni = 0; ni < 4; ni++) {
                    const int pb = ni >> 1, sub = ni & 1;
                    mma_s8(acc[mi][ni][0], acc[mi][ni][1],
                           acc[mi][ni][2], acc[mi][ni][3],
                           a[mi][0], a[mi][1], a[mi][2], a[mi][3],
                           b[pb][sub], b[pb][2 + sub]);
                }
            }
        }

        if ((p & (KT - 1)) == KT - 1) {
            // ---- tile epilogue: int16 store + fused column stats ----
            const int t = start + (p >> 5);
            const int tileM = t >> 4, tileN = t & 15;
            const int rowBase = tileM * BM + warpM * 64;
            const int colBase = tileN * BN + warpN * 32;

            int16_t* gout = g_gemm16 + (size_t)rowBase * Ndim + colBase;
            #pragma unroll
            for (int mi = 0; mi < 4; mi++) {
                #pragma unroll
                for (int ni = 0; ni < 4; ni++) {
                    int16_t* p0 = gout + (size_t)(mi * 16 + erow) * Ndim
                                + ni * 8 + ecol;
                    *reinterpret_cast<short2*>(p0) =
                        make_short2((int16_t)acc[mi][ni][0],
                                    (int16_t)acc[mi][ni][1]);
                    *reinterpret_cast<short2*>(p0 + (size_t)8 * Ndim) =
                        make_short2((int16_t)acc[mi][ni][2],
                                    (int16_t)acc[mi][ni][3]);
                }
            }

            const int chunk = tileM * 2 + warpM;    // 0..127
            #pragma unroll
            for (int ni = 0; ni < 4; ni++) {
                float s0 = 0.f, s1 = 0.f, q0 = 0.f, q1 = 0.f;
                #pragma unroll
                for (int mi = 0; mi < 4; mi++) {
                    float v0 = (float)acc[mi][ni][0];
                    float v1 = (float)acc[mi][ni][1];
                    float v2 = (float)acc[mi][ni][2];
                    float v3 = (float)acc[mi][ni][3];
                    s0 += v0 + v2;  s1 += v1 + v3;
                    q0 += v0 * v0 + v2 * v2;
                    q1 += v1 * v1 + v3 * v3;
                }
                #pragma unroll
                for (int off = 4; off < 32; off <<= 1) {
                    s0 += __shfl_xor_sync(0xffffffffu, s0, off);
                    s1 += __shfl_xor_sync(0xffffffffu, s1, off);
                    q0 += __shfl_xor_sync(0xffffffffu, q0, off);
                    q1 += __shfl_xor_sync(0xffffffffu, q1, off);
                }
                if (lane < 4) {
                    int c = colBase + ni * 8 + lane * 2;
                    g_psum[(size_t)chunk * Ndim + c]     = s0;
                    g_psum[(size_t)chunk * Ndim + c + 1] = s1;
                    g_psq [(size_t)chunk * Ndim + c]     = q0;
                    g_psq [(size_t)chunk * Ndim + c + 1] = q1;
                }
            }

            #pragma unroll
            for (int mi = 0; mi < 4; mi++)
                #pragma unroll
                for (int ni = 0; ni < 4; ni++)
                    #pragma unroll
                    for (int r = 0; r < 4; r++) acc[mi][ni][r] = 0;
        }
    }
}

// ---------------------------------------------------------------------------
// Kernel 5: finalize stats -> per-column scale/shift
// ---------------------------------------------------------------------------
__global__ void finalize_kernel(const float* __restrict__ gamma,
                                const float* __restrict__ beta) {
    int t = threadIdx.x;
    int col = blockIdx.x * 64 + (t >> 2);
    int slice = t & 3;
    float s = 0.f, q = 0.f;
    #pragma unroll 8
    for (int i = slice * 32; i < slice * 32 + 32; i++) {
        s += g_psum[(size_t)i * Ndim + col];
        q += g_psq [(size_t)i * Ndim + col];
    }
    s += __shfl_xor_sync(0xffffffffu, s, 1);
    q += __shfl_xor_sync(0xffffffffu, q, 1);
    s += __shfl_xor_sync(0xffffffffu, s, 2);
    q += __shfl_xor_sync(0xffffffffu, q, 2);
    if (slice == 0) {
        const float invB = 1.0f / (float)Mdim;
        float mean = s * invB;
        float var  = q * invB - mean * mean;
        float inv  = rsqrtf(var + 1e-5f);
        float sc   = gamma[col] * inv;
        g_scale[col] = sc;
        g_shift[col] = beta[col] - mean * sc;
    }
}

// ---------------------------------------------------------------------------
// Kernel 6: normalize into d_out (float4 scale/shift loads)
// ---------------------------------------------------------------------------
__global__ void normalize_kernel(float4* __restrict__ out) {
    int i = blockIdx.x * blockDim.x + threadIdx.x;
    int c4 = i & (Ndim / 4 - 1);
    short4 v = reinterpret_cast<const short4*>(g_gemm16)[i];
    float4 sc = reinterpret_cast<const float4*>(g_scale)[c4];
    float4 sh = reinterpret_cast<const float4*>(g_shift)[c4];
    float4 o;
    o.x = (float)v.x * sc.x + sh.x;
    o.y = (float)v.y * sc.y + sh.y;
    o.z = (float)v.z * sc.z + sh.z;
    o.w = (float)v.w * sc.w + sh.w;
    out[i] = o;
}

// ---------------------------------------------------------------------------
// Launch (GEMM at position 4 = ncu's observed capture slot)
// ---------------------------------------------------------------------------
extern "C" void kernel_launch(void* const* d_in, const int* in_sizes, int n_in,
                              void* d_out, int out_size) {
    const float* x     = (const float*)d_in[0];
    const float* w     = (const float*)d_in[1];
    const float* gamma = (const float*)d_in[2];
    const float* beta  = (const float*)d_in[3];
    float* out = (float*)d_out;

    binx_kernel<<<(Mdim * Kdim / 4) / 256, 256>>>((const float4*)x);   // 1
    binw_kernel<<<(Ndim * Kdim / 4) / 256, 256>>>((const float4*)w);   // 2
    pad_kernel<<<1, 32>>>();                                           // 3
    gemm_kernel<<<2 * NSM, 256>>>();                                   // 4
    finalize_kernel<<<Ndim / 64, 256>>>(gamma, beta);                  // 5
    normalize_kernel<<<(Mdim * Ndim / 4) / 256, 256>>>((float4*)out);  // 6
}

// round 12
// speedup vs baseline: 1.6269x; 1.4440x over previous
#include <cuda_runtime.h>
#include <cstdint>

// ---------------------------------------------------------------------------
// out = BN( sign(x) @ sign(W)^T ),  x[8192,2048], W[2048,2048] fp32.
// tcgen05 unavailable (harness assembles sm_103). R11 ncu: tensor pipe 89.8%
// busy, fma 2.1%, DRAM 0.5% -> legacy IMMA ceiling reached. This round runs
// TWO GEMM engines concurrently: tensor CTAs (mma.sync, bids 0..147) and
// dp4a CTAs (fma pipe, bids 148..295) pulling 128x128 tiles from one atomic
// work queue. Stats are exact integers -> output bit-identical regardless of
// which engine computes which tile (determinism under work stealing).
// ---------------------------------------------------------------------------

static constexpr int Mdim = 8192;
static constexpr int Ndim = 2048;
static constexpr int Kdim = 2048;

__device__ int8_t  g_xa[(size_t)Mdim * Kdim];          // 16 MB
__device__ int8_t  g_wa[(size_t)Ndim * Kdim];          //  4 MB
__device__ int16_t g_gemm16[(size_t)Mdim * Ndim];      // 32 MB (|val| <= 2048)
__device__ int     g_psum_i[128 * Ndim];               // per-64-row partials
__device__ int     g_psq_i [128 * Ndim];               // (exact int32)
__device__ float   g_scale[Ndim];
__device__ float   g_shift[Ndim];
__device__ int     g_next;                             // tile work queue

// ---------------------------------------------------------------------------
// Helpers
// ---------------------------------------------------------------------------
__device__ __forceinline__ uint32_t smem_u32(const void* p) {
    uint32_t r;
    asm("{ .reg .u64 t; cvta.to.shared.u64 t, %1; cvt.u32.u64 %0, t; }"
        : "=r"(r) : "l"(p));
    return r;
}

__device__ __forceinline__ void cp16(uint32_t saddr, const void* gaddr) {
    asm volatile("cp.async.cg.shared.global [%0], [%1], 16;"
                 :: "r"(saddr), "l"(gaddr));
}

// SW64 swizzle for 64-byte rows: bits[5:4] ^= bits[8:7]
__device__ __forceinline__ uint32_t swz64(uint32_t off) {
    return off ^ ((off >> 3) & 0x30);
}

#define LDSM_X4(R0, R1, R2, R3, addr)                                        \
    asm volatile("ldmatrix.sync.aligned.m8n8.x4.shared.b16 {%0,%1,%2,%3}, [%4];" \
                 : "=r"(R0), "=r"(R1), "=r"(R2), "=r"(R3) : "r"(addr))

__device__ __forceinline__ void mma_s8(int& c0, int& c1, int& c2, int& c3,
                                       uint32_t a0, uint32_t a1, uint32_t a2,
                                       uint32_t a3, uint32_t b0, uint32_t b1) {
    asm volatile(
        "mma.sync.aligned.m16n8k32.row.col.s32.s8.s8.s32 "
        "{%0,%1,%2,%3}, {%4,%5,%6,%7}, {%8,%9}, {%0,%1,%2,%3};"
        : "+r"(c0), "+r"(c1), "+r"(c2), "+r"(c3)
        : "r"(a0), "r"(a1), "r"(a2), "r"(a3), "r"(b0), "r"(b1));
}

// ---------------------------------------------------------------------------
// Kernels 1/2: binarize fp32 -> int8 {-1, 0, +1}
// ---------------------------------------------------------------------------
__device__ __forceinline__ int8_t sgn8(float a) {
    return (int8_t)((a > 0.0f) ? 1 : ((a < 0.0f) ? -1 : 0));
}

__global__ void binx_kernel(const float4* __restrict__ in) {
    int i = blockIdx.x * blockDim.x + threadIdx.x;
    float4 v = in[i];
    reinterpret_cast<char4*>(g_xa)[i] =
        make_char4(sgn8(v.x), sgn8(v.y), sgn8(v.z), sgn8(v.w));
}

__global__ void binw_kernel(const float4* __restrict__ in) {
    int i = blockIdx.x * blockDim.x + threadIdx.x;
    float4 v = in[i];
    reinterpret_cast<char4*>(g_wa)[i] =
        make_char4(sgn8(v.x), sgn8(v.y), sgn8(v.z), sgn8(v.w));
}

// Resets the work queue each graph replay (also keeps GEMM at ncu slot 4).
__global__ void pad_kernel() {
    if (threadIdx.x == 0) g_next = 0;
}

// ---------------------------------------------------------------------------
// Kernel 4: hybrid persistent GEMM, D = Xa @ Wa^T over 1024 128x128 tiles.
// bids 0..147: tensor path (mma.sync, flattened 4-stage cp.async pipeline).
// bids 148..295: dp4a path (fma pipe, double-buffered 128B k-chunks).
// Tiles pulled from a global atomic counter. Epilogue: int16 store + exact
// int column stats into g_psum_i/g_psq_i (chunk = 64-row granule).
// ---------------------------------------------------------------------------
static constexpr int BM = 128, BN = 128, BK = 64, STAGES = 4;
static constexpr int KT = Kdim / BK;                      // 32 ktiles / tile
static constexpr int NSM = 148;
static constexpr int NTILES = (Mdim / BM) * (Ndim / BN);  // 1024
static constexpr int A_BYTES = BM * BK;                   // 8 KB
static constexpr int B_BYTES = BN * BK;                   // 8 KB
static constexpr int STAGE_BYTES = A_BYTES + B_BYTES;     // 16 KB
// dp4a layout: per buffer, X half 128 rows x 144B (128B data + pad) then W.
static constexpr int XROW  = 144;
static constexpr int WOFF  = 128 * XROW;                  // 18432
static constexpr int DBUF  = 2 * WOFF;                    // 36864 per buffer
static constexpr int GEMM_SMEM = 2 * DBUF;                // 73728 (dyn)

__global__ void __launch_bounds__(256, 2)
gemm_kernel() {
    extern __shared__ __align__(1024) char smraw[];
    __shared__ int sh_next;

    const int tid  = threadIdx.x;
    const int lane = tid & 31;
    const uint32_t smBase = smem_u32(smraw);

    if (blockIdx.x < NSM) {
        // =================== TENSOR PATH ===================
        const int wid  = tid >> 5;
        const int warpM = wid >> 2;            // 0..1 -> 64 rows
        const int warpN = wid & 3;             // 0..3 -> 32 cols

        if (tid == 0) sh_next = atomicAdd(&g_next, 1);
        __syncthreads();
        int cur = sh_next;
        if (cur >= NTILES) return;

        auto load_ts = [&](int s, int t, int kt) {
            const int8_t* gA = g_xa + (size_t)(t >> 4) * BM * Kdim + kt * BK;
            const int8_t* gB = g_wa + (size_t)(t & 15) * BN * Kdim + kt * BK;
            uint32_t aBase = smBase + (uint32_t)s * STAGE_BYTES;
            uint32_t bBase = aBase + A_BYTES;
            #pragma unroll
            for (int i = 0; i < 2; i++) {
                int c = i * 256 + tid;
                int row = c >> 2, seg = c & 3;
                cp16(aBase + swz64((uint32_t)c * 16),
                     gA + (size_t)row * Kdim + seg * 16);
            }
            #pragma unroll
            for (int i = 0; i < 2; i++) {
                int c = i * 256 + tid;
                int row = c >> 2, seg = c & 3;
                cp16(bBase + swz64((uint32_t)c * 16),
                     gB + (size_t)row * Kdim + seg * 16);
            }
            asm volatile("cp.async.commit_group;" ::: "memory");
        };

        const int lrow = (lane & 7) + (((lane >> 3) & 1) << 3);
        const int lkb  = ((lane >> 4) & 1) * 16;
        uint32_t aoff[4], boff[2];
        #pragma unroll
        for (int mi = 0; mi < 4; mi++)
            aoff[mi] = (uint32_t)(warpM * 64 + mi * 16 + lrow) * BK + lkb;
        #pragma unroll
        for (int pb = 0; pb < 2; pb++)
            boff[pb] = (uint32_t)(warpN * 32 + pb * 16 + lrow) * BK + lkb;

        int acc[4][4][4];
        #pragma unroll
        for (int mi = 0; mi < 4; mi++)
            #pragma unroll
            for (int ni = 0; ni < 4; ni++)
                #pragma unroll
                for (int r = 0; r < 4; r++) acc[mi][ni][r] = 0;

        const int erow = lane >> 2;
        const int ecol = (lane & 3) * 2;

        // prologue: stages 0..2 of first tile
        #pragma unroll
        for (int s = 0; s < STAGES - 1; s++) load_ts(s, cur, s);

        int nxt = NTILES;
        while (true) {
            for (int kt = 0; kt < KT; kt++) {
                const int s = kt & (STAGES - 1);
                asm volatile("cp.async.wait_group %0;" :: "n"(STAGES - 2)
                             : "memory");
                __syncthreads();

                const int np = kt + STAGES - 1;
                const int ls = np & (STAGES - 1);
                if (np < KT) {
                    load_ts(ls, cur, np);
                } else {
                    if (np == KT) nxt = sh_next;   // fetched at kt == KT-4
                    if (nxt < NTILES)
                        load_ts(ls, nxt, np - KT);
                    else
                        asm volatile("cp.async.commit_group;" ::: "memory");
                }
                if (kt == KT - 4 && tid == 0)
                    sh_next = atomicAdd(&g_next, 1);

                const uint32_t aBase = smBase + (uint32_t)s * STAGE_BYTES;
                const uint32_t bBase = aBase + A_BYTES;
                #pragma unroll
                for (int k32 = 0; k32 < 2; k32++) {
                    uint32_t a[4][4], b[2][4];
                    #pragma unroll
                    for (int mi = 0; mi < 4; mi++)
                        LDSM_X4(a[mi][0], a[mi][1], a[mi][2], a[mi][3],
                                aBase + swz64(aoff[mi] + k32 * 32));
                    #pragma unroll
                    for (int pb = 0; pb < 2; pb++)
                        LDSM_X4(b[pb][0], b[pb][1], b[pb][2], b[pb][3],
                                bBase + swz64(boff[pb] + k32 * 32));
                    #pragma unroll
                    for (int mi = 0; mi < 4; mi++) {
                        #pragma unroll
                        for (int ni = 0; ni < 4; ni++) {
                            const int pb = ni >> 1, sub = ni & 1;
                            mma_s8(acc[mi][ni][0], acc[mi][ni][1],
                                   acc[mi][ni][2], acc[mi][ni][3],
                                   a[mi][0], a[mi][1], a[mi][2], a[mi][3],
                                   b[pb][sub], b[pb][2 + sub]);
                        }
                    }
                }
            }

            // ---- tile epilogue: int16 store + exact int column stats ----
            {
                const int tileM = cur >> 4, tileN = cur & 15;
                const int rowBase = tileM * BM + warpM * 64;
                const int colBase = tileN * BN + warpN * 32;
                int16_t* gout = g_gemm16 + (size_t)rowBase * Ndim + colBase;
                #pragma unroll
                for (int mi = 0; mi < 4; mi++) {
                    #pragma unroll
                    for (int ni = 0; ni < 4; ni++) {
                        int16_t* p0 = gout + (size_t)(mi * 16 + erow) * Ndim
                                    + ni * 8 + ecol;
                        *reinterpret_cast<short2*>(p0) =
                            make_short2((int16_t)acc[mi][ni][0],
                                        (int16_t)acc[mi][ni][1]);
                        *reinterpret_cast<short2*>(p0 + (size_t)8 * Ndim) =
                            make_short2((int16_t)acc[mi][ni][2],
                                        (int16_t)acc[mi][ni][3]);
                    }
                }
                const int chunk = tileM * 2 + warpM;
                #pragma unroll
                for (int ni = 0; ni < 4; ni++) {
                    int s0 = 0, s1 = 0, q0 = 0, q1 = 0;
                    #pragma unroll
                    for (int mi = 0; mi < 4; mi++) {
                        int a0 = acc[mi][ni][0], a1 = acc[mi][ni][1];
                        int a2 = acc[mi][ni][2], a3 = acc[mi][ni][3];
                        s0 += a0 + a2;  s1 += a1 + a3;
                        q0 += a0 * a0 + a2 * a2;
                        q1 += a1 * a1 + a3 * a3;
                    }
                    #pragma unroll
                    for (int off = 4; off < 32; off <<= 1) {
                        s0 += __shfl_xor_sync(0xffffffffu, s0, off);
                        s1 += __shfl_xor_sync(0xffffffffu, s1, off);
                        q0 += __shfl_xor_sync(0xffffffffu, q0, off);
                        q1 += __shfl_xor_sync(0xffffffffu, q1, off);
                    }
                    if (lane < 4) {
                        int c = colBase + ni * 8 + lane * 2;
                        g_psum_i[(size_t)chunk * Ndim + c]     = s0;
                        g_psum_i[(size_t)chunk * Ndim + c + 1] = s1;
                        g_psq_i [(size_t)chunk * Ndim + c]     = q0;
                        g_psq_i [(size_t)chunk * Ndim + c + 1] = q1;
                    }
                }
                #pragma unroll
                for (int mi = 0; mi < 4; mi++)
                    #pragma unroll
                    for (int ni = 0; ni < 4; ni++)
                        #pragma unroll
                        for (int r = 0; r < 4; r++) acc[mi][ni][r] = 0;
            }

            if (nxt >= NTILES) break;
            cur = nxt;
        }
    } else {
        // =================== DP4A PATH (fma pipe) ===================
        const int tr = tid >> 4;               // 0..15 -> 8-row group
        const int tc = tid & 15;               // 0..15 -> 8-col group

        while (true) {
            if (tid == 0) sh_next = atomicAdd(&g_next, 1);
            __syncthreads();
            const int t = sh_next;
            __syncthreads();
            if (t >= NTILES) break;

            const int tileM = t >> 4, tileN = t & 15;
            const int rowBase = tileM * BM, colBase = tileN * BN;

            int acc[8][8];
            #pragma unroll
            for (int i = 0; i < 8; i++)
                #pragma unroll
                for (int j = 0; j < 8; j++) acc[i][j] = 0;

            auto load_chunk = [&](int b, int c) {
                #pragma unroll
                for (int u = 0; u < 8; u++) {
                    int idx = u * 256 + tid;
                    int r = (idx & 1023) >> 3, seg = idx & 7;
                    if (idx < 1024) {
                        cp16(smBase + (uint32_t)(b * DBUF + r * XROW + seg * 16),
                             g_xa + (size_t)(rowBase + r) * Kdim + c * 128
                                  + seg * 16);
                    } else {
                        cp16(smBase + (uint32_t)(b * DBUF + WOFF + r * XROW
                                 + ((seg ^ ((r >> 3) & 7)) << 4)),
                             g_wa + (size_t)(colBase + r) * Kdim + c * 128
                                  + seg * 16);
                    }
                }
                asm volatile("cp.async.commit_group;" ::: "memory");
            };

            load_chunk(0, 0);
            for (int c = 0; c < 16; c++) {
                if (c + 1 < 16) {
                    load_chunk((c + 1) & 1, c + 1);
                    asm volatile("cp.async.wait_group 1;" ::: "memory");
                } else {
                    asm volatile("cp.async.wait_group 0;" ::: "memory");
                }
                __syncthreads();

                const char* xb = smraw + (c & 1) * DBUF;
                const char* wb = xb + WOFF;
                const int wsw = (tc & 7);
                #pragma unroll 4
                for (int kw = 0; kw < 32; kw++) {
                    int xw[8], ww[8];
                    #pragma unroll
                    for (int i = 0; i < 8; i++)
                        xw[i] = *(const int*)(xb + (tr * 8 + i) * XROW
                                              + kw * 4);
                    #pragma unroll
                    for (int j = 0; j < 8; j++)
                        ww[j] = *(const int*)(wb + (tc * 8 + j) * XROW
                                 + (((kw >> 2) ^ wsw) << 4) + ((kw & 3) << 2));
                    #pragma unroll
                    for (int i = 0; i < 8; i++)
                        #pragma unroll
                        for (int j = 0; j < 8; j++)
                            acc[i][j] = __dp4a(xw[i], ww[j], acc[i][j]);
                }
                __syncthreads();   // before next load overwrites this buffer
            }

            // ---- epilogue: int16 store + exact int stats via smem ----
            {
                int16_t* gout = g_gemm16
                              + (size_t)(rowBase + tr * 8) * Ndim
                              + colBase + tc * 8;
                #pragma unroll
                for (int i = 0; i < 8; i++) {
                    short tmp[8];
                    #pragma unroll
                    for (int j = 0; j < 8; j++) tmp[j] = (short)acc[i][j];
                    *reinterpret_cast<uint4*>(gout + (size_t)i * Ndim) =
                        *reinterpret_cast<uint4*>(tmp);
                }

                int* S = reinterpret_cast<int*>(smraw);        // [16][128]
                int* Q = S + 16 * 128;
                #pragma unroll
                for (int j = 0; j < 8; j++) {
                    int s = 0, q = 0;
                    #pragma unroll
                    for (int i = 0; i < 8; i++) {
                        s += acc[i][j];
                        q += acc[i][j] * acc[i][j];
                    }
                    S[tr * 128 + tc * 8 + j] = s;
                    Q[tr * 128 + tc * 8 + j] = q;
                }
                __syncthreads();
                {
                    int h = tid >> 7, cc = tid & 127;
                    int s = 0, q = 0;
                    #pragma unroll
                    for (int k = 0; k < 8; k++) {
                        s += S[(h * 8 + k) * 128 + cc];
                        q += Q[(h * 8 + k) * 128 + cc];
                    }
                    const int chunk = tileM * 2 + h;
                    g_psum_i[(size_t)chunk * Ndim + colBase + cc] = s;
                    g_psq_i [(size_t)chunk * Ndim + colBase + cc] = q;
                }
                __syncthreads();   // protect S/Q region before next tile
            }
        }
    }
}

// ---------------------------------------------------------------------------
// Kernel 5: finalize stats -> per-column scale/shift (exact ints -> double)
// ---------------------------------------------------------------------------
__global__ void finalize_kernel(const float* __restrict__ gamma,
                                const float* __restrict__ beta) {
    int t = threadIdx.x;
    int col = blockIdx.x * 64 + (t >> 2);
    int slice = t & 3;
    int s = 0;
    long long q = 0;
    #pragma unroll 8
    for (int i = slice * 32; i < slice * 32 + 32; i++) {
        s += g_psum_i[(size_t)i * Ndim + col];
        q += (long long)g_psq_i[(size_t)i * Ndim + col];
    }
    s += __shfl_xor_sync(0xffffffffu, s, 1);
    q += __shfl_xor_sync(0xffffffffu, q, 1);
    s += __shfl_xor_sync(0xffffffffu, s, 2);
    q += __shfl_xor_sync(0xffffffffu, q, 2);
    if (slice == 0) {
        double mean = (double)s / (double)Mdim;
        double var  = (double)q / (double)Mdim - mean * mean;
        float inv   = rsqrtf((float)(var + 1e-5));
        float sc    = gamma[col] * inv;
        g_scale[col] = sc;
        g_shift[col] = beta[col] - (float)mean * sc;
    }
}

// ---------------------------------------------------------------------------
// Kernel 6: normalize into d_out (float4 scale/shift loads)
// ---------------------------------------------------------------------------
__global__ void normalize_kernel(float4* __restrict__ out) {
    int i = blockIdx.x * blockDim.x + threadIdx.x;
    int c4 = i & (Ndim / 4 - 1);
    short4 v = reinterpret_cast<const short4*>(g_gemm16)[i];
    float4 sc = reinterpret_cast<const float4*>(g_scale)[c4];
    float4 sh = reinterpret_cast<const float4*>(g_shift)[c4];
    float4 o;
    o.x = (float)v.x * sc.x + sh.x;
    o.y = (float)v.y * sc.y + sh.y;
    o.z = (float)v.z * sc.z + sh.z;
    o.w = (float)v.w * sc.w + sh.w;
    out[i] = o;
}

// ---------------------------------------------------------------------------
// Launch (GEMM at position 4 = ncu's observed capture slot)
// ---------------------------------------------------------------------------
extern "C" void kernel_launch(void* const* d_in, const int* in_sizes, int n_in,
                              void* d_out, int out_size) {
    const float* x     = (const float*)d_in[0];
    const float* w     = (const float*)d_in[1];
    const float* gamma = (const float*)d_in[2];
    const float* beta  = (const float*)d_in[3];
    float* out = (float*)d_out;

    cudaFuncSetAttribute(gemm_kernel,
                         cudaFuncAttributeMaxDynamicSharedMemorySize,
                         GEMM_SMEM);

    binx_kernel<<<(Mdim * Kdim / 4) / 256, 256>>>((const float4*)x);   // 1
    binw_kernel<<<(Ndim * Kdim / 4) / 256, 256>>>((const float4*)w);   // 2
    pad_kernel<<<1, 32>>>();                                           // 3
    gemm_kernel<<<2 * NSM, 256, GEMM_SMEM>>>();                        // 4
    finalize_kernel<<<Ndim / 64, 256>>>(gamma, beta);                  // 5
    normalize_kernel<<<(Mdim * Ndim / 4) / 256, 256>>>((float4*)out);  // 6
}